// round 14
// baseline (speedup 1.0000x reference)
#include <cuda_runtime.h>
#include <cuda_bf16.h>
#include <cstdint>

// ---------------------------------------------------------------------------
// 16-node DAG: y_i = tanh((y_{i-1} + y_{i-2}) @ W_i + b_i), B=4096, D=2048 fp32.
// bf16x3 split GEMM on mma.sync, with:
//   - prepass splitting W and x into k-pair-packed u32 bf16 hi/lo planes
//   - cp.async double-buffered mainloop (no conversion, no reg staging)
//   - epilogue emits next node's pre-summed, pre-split A operand
//   - __launch_bounds__(256,2) for 2 CTAs/SM
// ---------------------------------------------------------------------------

namespace {
constexpr int NBATCH   = 4096;
constexpr int ND       = 2048;
constexpr int NKP      = ND / 2;       // 1024 k-pairs
constexpr int BM       = 128;
constexpr int BN       = 128;
constexpr int KTILES   = ND / 32;      // 64
constexpr int NTHREADS = 256;
constexpr int ASTR     = 20;           // u32 stride per A smem row (16 used + 4 pad)
constexpr int BSTR     = 136;          // u32 stride per B smem row (128 used + 8 pad)
constexpr int APL      = BM * ASTR;    // 2560 u32 per A plane
constexpr int BPL      = 16 * BSTR;    // 2176 u32 per B plane
constexpr int B_OFS    = 2 * APL;      // 5120
constexpr int STAGE_U32 = 2 * APL + 2 * BPL;     // 9472 u32 = 37888 B
constexpr int SMEM_BYTES = 2 * STAGE_U32 * 4;    // 75776 B (2 stages)
constexpr int N_NODES  = 16;
}

// Packed bf16 hi/lo planes (u32 = two adjacent-k bf16). Static device globals
// are the sanctioned scratch mechanism.
__device__ __align__(16) static uint32_t g_Whi[(size_t)N_NODES * NKP * ND];   // 128 MB
__device__ __align__(16) static uint32_t g_Wlo[(size_t)N_NODES * NKP * ND];   // 128 MB
__device__ __align__(16) static uint32_t g_S[2][2][(size_t)NBATCH * NKP];     // sum planes [slot][hi/lo]
__device__ __align__(16) static uint32_t g_Y[2][2][(size_t)NBATCH * NKP];     // activation planes

__device__ __forceinline__ uint32_t packu(__nv_bfloat16 a, __nv_bfloat16 b) {
    return (uint32_t)__bfloat16_as_ushort(a) | ((uint32_t)__bfloat16_as_ushort(b) << 16);
}
__device__ __forceinline__ void split2(float v0, float v1, uint32_t& hi, uint32_t& lo) {
    __nv_bfloat16 h0 = __float2bfloat16(v0), h1 = __float2bfloat16(v1);
    hi = packu(h0, h1);
    lo = packu(__float2bfloat16(v0 - __bfloat162float(h0)),
               __float2bfloat16(v1 - __bfloat162float(h1)));
}
__device__ __forceinline__ float lo16f(uint32_t v) {
    return __bfloat162float(__ushort_as_bfloat16((unsigned short)(v & 0xffffu)));
}
__device__ __forceinline__ float hi16f(uint32_t v) {
    return __bfloat162float(__ushort_as_bfloat16((unsigned short)(v >> 16)));
}

__device__ __forceinline__ void mma_bf16(float& c0, float& c1, float& c2, float& c3,
                                         uint32_t a0, uint32_t a1, uint32_t a2, uint32_t a3,
                                         uint32_t b0, uint32_t b1) {
    asm volatile(
        "mma.sync.aligned.m16n8k16.row.col.f32.bf16.bf16.f32 "
        "{%0,%1,%2,%3},{%4,%5,%6,%7},{%8,%9},{%0,%1,%2,%3};\n"
        : "+f"(c0), "+f"(c1), "+f"(c2), "+f"(c3)
        : "r"(a0), "r"(a1), "r"(a2), "r"(a3), "r"(b0), "r"(b1));
}

// ---------------------------------------------------------------------------
// Prepass: split W into k-pair-packed bf16 hi/lo planes (along k = W rows).
__global__ void split_w_kernel(const float* __restrict__ W) {
    size_t i = (size_t)blockIdx.x * NTHREADS + threadIdx.x;   // over 16*1024*2048
    size_t per_node = (size_t)NKP * ND;                       // 2^21
    int node = (int)(i >> 21);
    size_t rem = i & (per_node - 1);
    int kp  = (int)(rem >> 11);                                // /2048
    int col = (int)(rem & 2047);
    const float* p = W + (size_t)node * ND * ND + (size_t)(2 * kp) * ND + col;
    uint32_t hi, lo;
    split2(p[0], p[ND], hi, lo);
    g_Whi[i] = hi;
    g_Wlo[i] = lo;
}

// Split x (k = columns, adjacent) into g_S[0] planes.
__global__ void split_x_kernel(const float* __restrict__ x) {
    size_t i = (size_t)blockIdx.x * NTHREADS + threadIdx.x;   // over 4096*1024
    float2 v = reinterpret_cast<const float2*>(x)[i];
    uint32_t hi, lo;
    split2(v.x, v.y, hi, lo);
    g_S[0][0][i] = hi;
    g_S[0][1][i] = lo;
}

// ---------------------------------------------------------------------------
// One DAG node GEMM: reads A planes g_S[a_slot], B planes g_W*[node].
// Epilogue: tanh(+bias); writes y planes (yo_slot), s_{i+1} planes (so_slot,
// adding y_{i-1} from yp_slot), and/or fp32 d_out.
__global__ void __launch_bounds__(NTHREADS, 2)
dag_gemm(const float* __restrict__ bn, float* __restrict__ dout,
         int node, int a_slot, int yp_slot, int yo_slot, int so_slot, int write_out)
{
    extern __shared__ uint32_t sm[];

    const uint32_t* __restrict__ Ah = g_S[a_slot][0];
    const uint32_t* __restrict__ Al = g_S[a_slot][1];
    const uint32_t* __restrict__ Wh = g_Whi + (size_t)node * NKP * ND;
    const uint32_t* __restrict__ Wl = g_Wlo + (size_t)node * NKP * ND;

    const int tid  = threadIdx.x;
    const int lane = tid & 31;
    const int wid  = tid >> 5;
    const int g    = lane >> 2;
    const int t    = lane & 3;
    const int wm   = (wid >> 2) * 64;
    const int wn   = (wid & 3) * 32;
    const int m0   = blockIdx.y * BM;
    const int n0   = blockIdx.x * BN;

    const uint32_t smem_base = (uint32_t)__cvta_generic_to_shared(sm);

    float acc[4][4][4];
    #pragma unroll
    for (int mi = 0; mi < 4; mi++)
        #pragma unroll
        for (int ni = 0; ni < 4; ni++)
            #pragma unroll
            for (int q = 0; q < 4; q++)
                acc[mi][ni][q] = 0.0f;

    auto load_tiles = [&](int kt, int stg) {
        uint32_t sb = smem_base + (uint32_t)(stg * (STAGE_U32 * 4));
        // A tiles: 2 planes x 128 rows x 16 u32 -> 1024 x 16B chunks
        #pragma unroll
        for (int i = 0; i < 4; i++) {
            int e  = tid + i * NTHREADS;
            int pl = e >> 9;
            int r  = (e >> 2) & 127;
            int c  = e & 3;
            const uint32_t* src = (pl ? Al : Ah) + (size_t)(m0 + r) * NKP + kt * 16 + c * 4;
            uint32_t dst = sb + (uint32_t)((pl * APL + r * ASTR + c * 4) * 4);
            asm volatile("cp.async.cg.shared.global [%0], [%1], 16;\n" :: "r"(dst), "l"(src));
        }
        // B tiles: 2 planes x 16 kk x 128 u32 -> 1024 x 16B chunks
        #pragma unroll
        for (int i = 0; i < 4; i++) {
            int e  = tid + i * NTHREADS;
            int pl = e >> 9;
            int kk = (e >> 5) & 15;
            int c  = e & 31;
            const uint32_t* src = (pl ? Wl : Wh) + (size_t)(kt * 16 + kk) * ND + n0 + c * 4;
            uint32_t dst = sb + (uint32_t)((B_OFS + pl * BPL + kk * BSTR + c * 4) * 4);
            asm volatile("cp.async.cg.shared.global [%0], [%1], 16;\n" :: "r"(dst), "l"(src));
        }
        asm volatile("cp.async.commit_group;\n");
    };

    load_tiles(0, 0);

    #pragma unroll 1
    for (int kt = 0; kt < KTILES; ++kt) {
        const int cur = kt & 1;
        if (kt + 1 < KTILES) {
            load_tiles(kt + 1, cur ^ 1);
            asm volatile("cp.async.wait_group 1;\n");
        } else {
            asm volatile("cp.async.wait_group 0;\n");
        }
        __syncthreads();

        const int ab = cur * STAGE_U32;          // A hi base (u32 index into sm)
        #pragma unroll
        for (int s = 0; s < 2; s++) {
            uint32_t bh[4][2], bl[4][2];
            #pragma unroll
            for (int ni = 0; ni < 4; ni++) {
                int c  = wn + ni * 8 + g;
                int r0 = ab + B_OFS + (s * 8 + t) * BSTR + c;
                bh[ni][0] = sm[r0];
                bh[ni][1] = sm[r0 + 4 * BSTR];
                bl[ni][0] = sm[r0 + BPL];
                bl[ni][1] = sm[r0 + BPL + 4 * BSTR];
            }
            #pragma unroll
            for (int mi = 0; mi < 4; mi++) {
                int r = wm + mi * 16 + g;
                int p = ab + r * ASTR + s * 8 + t;
                uint32_t a0 = sm[p];
                uint32_t a1 = sm[p + 8 * ASTR];
                uint32_t a2 = sm[p + 4];
                uint32_t a3 = sm[p + 8 * ASTR + 4];
                uint32_t l0 = sm[p + APL];
                uint32_t l1 = sm[p + APL + 8 * ASTR];
                uint32_t l2 = sm[p + APL + 4];
                uint32_t l3 = sm[p + APL + 8 * ASTR + 4];
                #pragma unroll
                for (int ni = 0; ni < 4; ni++) {
                    mma_bf16(acc[mi][ni][0], acc[mi][ni][1], acc[mi][ni][2], acc[mi][ni][3],
                             a0, a1, a2, a3, bh[ni][0], bh[ni][1]);
                    mma_bf16(acc[mi][ni][0], acc[mi][ni][1], acc[mi][ni][2], acc[mi][ni][3],
                             a0, a1, a2, a3, bl[ni][0], bl[ni][1]);
                    mma_bf16(acc[mi][ni][0], acc[mi][ni][1], acc[mi][ni][2], acc[mi][ni][3],
                             l0, l1, l2, l3, bh[ni][0], bh[ni][1]);
                }
            }
        }
        __syncthreads();
    }

    // -------------------- epilogue --------------------
    uint32_t* __restrict__ Yoh = (yo_slot >= 0) ? g_Y[yo_slot][0] : nullptr;
    uint32_t* __restrict__ Yol = (yo_slot >= 0) ? g_Y[yo_slot][1] : nullptr;
    const uint32_t* __restrict__ Yph = (yp_slot >= 0) ? g_Y[yp_slot][0] : nullptr;
    const uint32_t* __restrict__ Ypl = (yp_slot >= 0) ? g_Y[yp_slot][1] : nullptr;
    uint32_t* __restrict__ Soh = (so_slot >= 0) ? g_S[so_slot][0] : nullptr;
    uint32_t* __restrict__ Sol = (so_slot >= 0) ? g_S[so_slot][1] : nullptr;

    #pragma unroll
    for (int mi = 0; mi < 4; mi++) {
        #pragma unroll
        for (int ni = 0; ni < 4; ni++) {
            int colp = ((n0 + wn + ni * 8) >> 1) + t;     // u32 column in planes
            float b0 = bn[2 * colp];
            float b1 = bn[2 * colp + 1];
            #pragma unroll
            for (int h = 0; h < 2; h++) {
                int row = m0 + wm + mi * 16 + g + h * 8;
                float t0 = tanhf(acc[mi][ni][2 * h]     + b0);
                float t1 = tanhf(acc[mi][ni][2 * h + 1] + b1);
                size_t idx = (size_t)row * NKP + colp;
                if (write_out) {
                    float2 r2;
                    r2.x = t0; r2.y = t1;
                    *reinterpret_cast<float2*>(dout + (size_t)row * ND + 2 * colp) = r2;
                }
                if (Yoh) {
                    uint32_t hi, lo;
                    split2(t0, t1, hi, lo);
                    Yoh[idx] = hi; Yol[idx] = lo;
                }
                if (Soh) {
                    float s0 = t0, s1 = t1;
                    if (Yph) {
                        uint32_t ph = Yph[idx], pl = Ypl[idx];
                        s0 += lo16f(ph) + lo16f(pl);
                        s1 += hi16f(ph) + hi16f(pl);
                    }
                    uint32_t hi, lo;
                    split2(s0, s1, hi, lo);
                    Soh[idx] = hi; Sol[idx] = lo;
                }
            }
        }
    }
}

extern "C" void kernel_launch(void* const* d_in, const int* in_sizes, int n_in,
                              void* d_out, int out_size) {
    const float* x = (const float*)d_in[0];          // [4096, 2048]
    const float* W = (const float*)d_in[1];          // [16, 2048, 2048]
    const float* b = (const float*)d_in[2];          // [16, 2048]
    float* out = (float*)d_out;                      // [4096, 2048]

    cudaFuncSetAttribute(dag_gemm, cudaFuncAttributeMaxDynamicSharedMemorySize, SMEM_BYTES);

    // Prepass: pack W and x into bf16 hi/lo k-pair planes.
    split_w_kernel<<<(N_NODES * NKP * ND) / NTHREADS, NTHREADS>>>(W);   // 131072 blocks
    split_x_kernel<<<(NBATCH * NKP) / NTHREADS, NTHREADS>>>(x);         // 16384 blocks

    dim3 grid(ND / BN, NBATCH / BM);                 // (16, 32) = 512 CTAs

    for (int i = 0; i < N_NODES; i++) {
        int a_slot = i & 1;                           // s_i planes (x for node 0)
        int yp = (i >= 1 && i <= 14) ? ((i - 1) & 1) : -1;   // y_{i-1} for the s-sum
        int yo = (i <= 13) ? (i & 1) : -1;            // y_i planes (consumed by node i+1 epilogue)
        int so = (i <= 14) ? ((i + 1) & 1) : -1;      // s_{i+1} planes
        int wo = (i == N_NODES - 1) ? 1 : 0;
        dag_gemm<<<grid, NTHREADS, SMEM_BYTES>>>(b + (size_t)i * ND, out,
                                                 i, a_slot, yp, yo, so, wo);
    }
}

// round 15
// speedup vs baseline: 1.0000x; 1.0000x over previous
#include <cuda_runtime.h>
#include <cuda_bf16.h>
#include <cstdint>

// ---------------------------------------------------------------------------
// 16-node DAG: y_i = tanh((y_{i-1} + y_{i-2}) @ W_i + b_i), B=4096, D=2048 fp32.
// bf16x3 split GEMM on mma.sync, with:
//   - prepass splitting W and x into k-pair-packed u32 bf16 hi/lo planes
//   - cp.async double-buffered mainloop (no conversion, no reg staging)
//   - epilogue emits next node's pre-summed, pre-split A operand
//   - __launch_bounds__(256,2) for 2 CTAs/SM
// ---------------------------------------------------------------------------

namespace {
constexpr int NBATCH   = 4096;
constexpr int ND       = 2048;
constexpr int NKP      = ND / 2;       // 1024 k-pairs
constexpr int BM       = 128;
constexpr int BN       = 128;
constexpr int KTILES   = ND / 32;      // 64
constexpr int NTHREADS = 256;
constexpr int ASTR     = 20;           // u32 stride per A smem row (16 used + 4 pad)
constexpr int BSTR     = 136;          // u32 stride per B smem row (128 used + 8 pad)
constexpr int APL      = BM * ASTR;    // 2560 u32 per A plane
constexpr int BPL      = 16 * BSTR;    // 2176 u32 per B plane
constexpr int B_OFS    = 2 * APL;      // 5120
constexpr int STAGE_U32 = 2 * APL + 2 * BPL;     // 9472 u32 = 37888 B
constexpr int SMEM_BYTES = 2 * STAGE_U32 * 4;    // 75776 B (2 stages)
constexpr int N_NODES  = 16;
}

// Packed bf16 hi/lo planes (u32 = two adjacent-k bf16). Static device globals
// are the sanctioned scratch mechanism.
__device__ __align__(16) static uint32_t g_Whi[(size_t)N_NODES * NKP * ND];   // 128 MB
__device__ __align__(16) static uint32_t g_Wlo[(size_t)N_NODES * NKP * ND];   // 128 MB
__device__ __align__(16) static uint32_t g_S[2][2][(size_t)NBATCH * NKP];     // sum planes [slot][hi/lo]
__device__ __align__(16) static uint32_t g_Y[2][2][(size_t)NBATCH * NKP];     // activation planes

__device__ __forceinline__ uint32_t packu(__nv_bfloat16 a, __nv_bfloat16 b) {
    return (uint32_t)__bfloat16_as_ushort(a) | ((uint32_t)__bfloat16_as_ushort(b) << 16);
}
__device__ __forceinline__ void split2(float v0, float v1, uint32_t& hi, uint32_t& lo) {
    __nv_bfloat16 h0 = __float2bfloat16(v0), h1 = __float2bfloat16(v1);
    hi = packu(h0, h1);
    lo = packu(__float2bfloat16(v0 - __bfloat162float(h0)),
               __float2bfloat16(v1 - __bfloat162float(h1)));
}
__device__ __forceinline__ float lo16f(uint32_t v) {
    return __bfloat162float(__ushort_as_bfloat16((unsigned short)(v & 0xffffu)));
}
__device__ __forceinline__ float hi16f(uint32_t v) {
    return __bfloat162float(__ushort_as_bfloat16((unsigned short)(v >> 16)));
}

__device__ __forceinline__ void mma_bf16(float& c0, float& c1, float& c2, float& c3,
                                         uint32_t a0, uint32_t a1, uint32_t a2, uint32_t a3,
                                         uint32_t b0, uint32_t b1) {
    asm volatile(
        "mma.sync.aligned.m16n8k16.row.col.f32.bf16.bf16.f32 "
        "{%0,%1,%2,%3},{%4,%5,%6,%7},{%8,%9},{%0,%1,%2,%3};\n"
        : "+f"(c0), "+f"(c1), "+f"(c2), "+f"(c3)
        : "r"(a0), "r"(a1), "r"(a2), "r"(a3), "r"(b0), "r"(b1));
}

// ---------------------------------------------------------------------------
// Prepass: split W into k-pair-packed bf16 hi/lo planes (along k = W rows).
__global__ void split_w_kernel(const float* __restrict__ W) {
    size_t i = (size_t)blockIdx.x * NTHREADS + threadIdx.x;   // over 16*1024*2048
    size_t per_node = (size_t)NKP * ND;                       // 2^21
    int node = (int)(i >> 21);
    size_t rem = i & (per_node - 1);
    int kp  = (int)(rem >> 11);                                // /2048
    int col = (int)(rem & 2047);
    const float* p = W + (size_t)node * ND * ND + (size_t)(2 * kp) * ND + col;
    uint32_t hi, lo;
    split2(p[0], p[ND], hi, lo);
    g_Whi[i] = hi;
    g_Wlo[i] = lo;
}

// Split x (k = columns, adjacent) into g_S[0] planes.
__global__ void split_x_kernel(const float* __restrict__ x) {
    size_t i = (size_t)blockIdx.x * NTHREADS + threadIdx.x;   // over 4096*1024
    float2 v = reinterpret_cast<const float2*>(x)[i];
    uint32_t hi, lo;
    split2(v.x, v.y, hi, lo);
    g_S[0][0][i] = hi;
    g_S[0][1][i] = lo;
}

// ---------------------------------------------------------------------------
// One DAG node GEMM: reads A planes g_S[a_slot], B planes g_W*[node].
// Epilogue: tanh(+bias); writes y planes (yo_slot), s_{i+1} planes (so_slot,
// adding y_{i-1} from yp_slot), and/or fp32 d_out.
__global__ void __launch_bounds__(NTHREADS, 2)
dag_gemm(const float* __restrict__ bn, float* __restrict__ dout,
         int node, int a_slot, int yp_slot, int yo_slot, int so_slot, int write_out)
{
    extern __shared__ uint32_t sm[];

    const uint32_t* __restrict__ Ah = g_S[a_slot][0];
    const uint32_t* __restrict__ Al = g_S[a_slot][1];
    const uint32_t* __restrict__ Wh = g_Whi + (size_t)node * NKP * ND;
    const uint32_t* __restrict__ Wl = g_Wlo + (size_t)node * NKP * ND;

    const int tid  = threadIdx.x;
    const int lane = tid & 31;
    const int wid  = tid >> 5;
    const int g    = lane >> 2;
    const int t    = lane & 3;
    const int wm   = (wid >> 2) * 64;
    const int wn   = (wid & 3) * 32;
    const int m0   = blockIdx.y * BM;
    const int n0   = blockIdx.x * BN;

    const uint32_t smem_base = (uint32_t)__cvta_generic_to_shared(sm);

    float acc[4][4][4];
    #pragma unroll
    for (int mi = 0; mi < 4; mi++)
        #pragma unroll
        for (int ni = 0; ni < 4; ni++)
            #pragma unroll
            for (int q = 0; q < 4; q++)
                acc[mi][ni][q] = 0.0f;

    auto load_tiles = [&](int kt, int stg) {
        uint32_t sb = smem_base + (uint32_t)(stg * (STAGE_U32 * 4));
        // A tiles: 2 planes x 128 rows x 16 u32 -> 1024 x 16B chunks
        #pragma unroll
        for (int i = 0; i < 4; i++) {
            int e  = tid + i * NTHREADS;
            int pl = e >> 9;
            int r  = (e >> 2) & 127;
            int c  = e & 3;
            const uint32_t* src = (pl ? Al : Ah) + (size_t)(m0 + r) * NKP + kt * 16 + c * 4;
            uint32_t dst = sb + (uint32_t)((pl * APL + r * ASTR + c * 4) * 4);
            asm volatile("cp.async.cg.shared.global [%0], [%1], 16;\n" :: "r"(dst), "l"(src));
        }
        // B tiles: 2 planes x 16 kk x 128 u32 -> 1024 x 16B chunks
        #pragma unroll
        for (int i = 0; i < 4; i++) {
            int e  = tid + i * NTHREADS;
            int pl = e >> 9;
            int kk = (e >> 5) & 15;
            int c  = e & 31;
            const uint32_t* src = (pl ? Wl : Wh) + (size_t)(kt * 16 + kk) * ND + n0 + c * 4;
            uint32_t dst = sb + (uint32_t)((B_OFS + pl * BPL + kk * BSTR + c * 4) * 4);
            asm volatile("cp.async.cg.shared.global [%0], [%1], 16;\n" :: "r"(dst), "l"(src));
        }
        asm volatile("cp.async.commit_group;\n");
    };

    load_tiles(0, 0);

    #pragma unroll 1
    for (int kt = 0; kt < KTILES; ++kt) {
        const int cur = kt & 1;
        if (kt + 1 < KTILES) {
            load_tiles(kt + 1, cur ^ 1);
            asm volatile("cp.async.wait_group 1;\n");
        } else {
            asm volatile("cp.async.wait_group 0;\n");
        }
        __syncthreads();

        const int ab = cur * STAGE_U32;          // A hi base (u32 index into sm)
        #pragma unroll
        for (int s = 0; s < 2; s++) {
            uint32_t bh[4][2], bl[4][2];
            #pragma unroll
            for (int ni = 0; ni < 4; ni++) {
                int c  = wn + ni * 8 + g;
                int r0 = ab + B_OFS + (s * 8 + t) * BSTR + c;
                bh[ni][0] = sm[r0];
                bh[ni][1] = sm[r0 + 4 * BSTR];
                bl[ni][0] = sm[r0 + BPL];
                bl[ni][1] = sm[r0 + BPL + 4 * BSTR];
            }
            #pragma unroll
            for (int mi = 0; mi < 4; mi++) {
                int r = wm + mi * 16 + g;
                int p = ab + r * ASTR + s * 8 + t;
                uint32_t a0 = sm[p];
                uint32_t a1 = sm[p + 8 * ASTR];
                uint32_t a2 = sm[p + 4];
                uint32_t a3 = sm[p + 8 * ASTR + 4];
                uint32_t l0 = sm[p + APL];
                uint32_t l1 = sm[p + APL + 8 * ASTR];
                uint32_t l2 = sm[p + APL + 4];
                uint32_t l3 = sm[p + APL + 8 * ASTR + 4];
                #pragma unroll
                for (int ni = 0; ni < 4; ni++) {
                    mma_bf16(acc[mi][ni][0], acc[mi][ni][1], acc[mi][ni][2], acc[mi][ni][3],
                             a0, a1, a2, a3, bh[ni][0], bh[ni][1]);
                    mma_bf16(acc[mi][ni][0], acc[mi][ni][1], acc[mi][ni][2], acc[mi][ni][3],
                             a0, a1, a2, a3, bl[ni][0], bl[ni][1]);
                    mma_bf16(acc[mi][ni][0], acc[mi][ni][1], acc[mi][ni][2], acc[mi][ni][3],
                             l0, l1, l2, l3, bh[ni][0], bh[ni][1]);
                }
            }
        }
        __syncthreads();
    }

    // -------------------- epilogue --------------------
    uint32_t* __restrict__ Yoh = (yo_slot >= 0) ? g_Y[yo_slot][0] : nullptr;
    uint32_t* __restrict__ Yol = (yo_slot >= 0) ? g_Y[yo_slot][1] : nullptr;
    const uint32_t* __restrict__ Yph = (yp_slot >= 0) ? g_Y[yp_slot][0] : nullptr;
    const uint32_t* __restrict__ Ypl = (yp_slot >= 0) ? g_Y[yp_slot][1] : nullptr;
    uint32_t* __restrict__ Soh = (so_slot >= 0) ? g_S[so_slot][0] : nullptr;
    uint32_t* __restrict__ Sol = (so_slot >= 0) ? g_S[so_slot][1] : nullptr;

    #pragma unroll
    for (int mi = 0; mi < 4; mi++) {
        #pragma unroll
        for (int ni = 0; ni < 4; ni++) {
            int colp = ((n0 + wn + ni * 8) >> 1) + t;     // u32 column in planes
            float b0 = bn[2 * colp];
            float b1 = bn[2 * colp + 1];
            #pragma unroll
            for (int h = 0; h < 2; h++) {
                int row = m0 + wm + mi * 16 + g + h * 8;
                float t0 = tanhf(acc[mi][ni][2 * h]     + b0);
                float t1 = tanhf(acc[mi][ni][2 * h + 1] + b1);
                size_t idx = (size_t)row * NKP + colp;
                if (write_out) {
                    float2 r2;
                    r2.x = t0; r2.y = t1;
                    *reinterpret_cast<float2*>(dout + (size_t)row * ND + 2 * colp) = r2;
                }
                if (Yoh) {
                    uint32_t hi, lo;
                    split2(t0, t1, hi, lo);
                    Yoh[idx] = hi; Yol[idx] = lo;
                }
                if (Soh) {
                    float s0 = t0, s1 = t1;
                    if (Yph) {
                        uint32_t ph = Yph[idx], pl = Ypl[idx];
                        s0 += lo16f(ph) + lo16f(pl);
                        s1 += hi16f(ph) + hi16f(pl);
                    }
                    uint32_t hi, lo;
                    split2(s0, s1, hi, lo);
                    Soh[idx] = hi; Sol[idx] = lo;
                }
            }
        }
    }
}

extern "C" void kernel_launch(void* const* d_in, const int* in_sizes, int n_in,
                              void* d_out, int out_size) {
    const float* x = (const float*)d_in[0];          // [4096, 2048]
    const float* W = (const float*)d_in[1];          // [16, 2048, 2048]
    const float* b = (const float*)d_in[2];          // [16, 2048]
    float* out = (float*)d_out;                      // [4096, 2048]

    cudaFuncSetAttribute(dag_gemm, cudaFuncAttributeMaxDynamicSharedMemorySize, SMEM_BYTES);

    // Prepass: pack W and x into bf16 hi/lo k-pair planes.
    split_w_kernel<<<(N_NODES * NKP * ND) / NTHREADS, NTHREADS>>>(W);   // 131072 blocks
    split_x_kernel<<<(NBATCH * NKP) / NTHREADS, NTHREADS>>>(x);         // 16384 blocks

    dim3 grid(ND / BN, NBATCH / BM);                 // (16, 32) = 512 CTAs

    for (int i = 0; i < N_NODES; i++) {
        int a_slot = i & 1;                           // s_i planes (x for node 0)
        int yp = (i >= 1 && i <= 14) ? ((i - 1) & 1) : -1;   // y_{i-1} for the s-sum
        int yo = (i <= 13) ? (i & 1) : -1;            // y_i planes (consumed by node i+1 epilogue)
        int so = (i <= 14) ? ((i + 1) & 1) : -1;      // s_{i+1} planes
        int wo = (i == N_NODES - 1) ? 1 : 0;
        dag_gemm<<<grid, NTHREADS, SMEM_BYTES>>>(b + (size_t)i * ND, out,
                                                 i, a_slot, yp, yo, so, wo);
    }
}

// round 17
// speedup vs baseline: 1.0330x; 1.0330x over previous
#include <cuda_runtime.h>
#include <cuda_bf16.h>
#include <cstdint>

// ---------------------------------------------------------------------------
// 16-node DAG: y_i = tanh((y_{i-1} + y_{i-2}) @ W_i + b_i), B=4096, D=2048 fp32.
// bf16x3 split GEMM on mma.sync (tcgen05 unavailable: toolchain targets sm_103
// without the 'a' feature set), with:
//   - prepass splitting W and x into k-pair-packed u32 bf16 hi/lo planes
//   - cp.async double-buffered mainloop (no conversion, no reg staging)
//   - TERM-MAJOR MMA issue order: 16 independent HMMAs between accumulator
//     reuses (was 3 dependent MMAs back-to-back -> RAW-latency bound)
//   - epilogue emits next node's pre-summed, pre-split A operand
// ---------------------------------------------------------------------------

namespace {
constexpr int NBATCH   = 4096;
constexpr int ND       = 2048;
constexpr int NKP      = ND / 2;       // 1024 k-pairs
constexpr int BM       = 128;
constexpr int BN       = 128;
constexpr int KTILES   = ND / 32;      // 64
constexpr int NTHREADS = 256;
constexpr int ASTR     = 20;           // u32 stride per A smem row (16 used + 4 pad)
constexpr int BSTR     = 136;          // u32 stride per B smem row (128 used + 8 pad)
constexpr int APL      = BM * ASTR;    // 2560 u32 per A plane
constexpr int BPL      = 16 * BSTR;    // 2176 u32 per B plane
constexpr int B_OFS    = 2 * APL;      // 5120
constexpr int STAGE_U32 = 2 * APL + 2 * BPL;     // 9472 u32 = 37888 B
constexpr int SMEM_BYTES = 2 * STAGE_U32 * 4;    // 75776 B (2 stages)
constexpr int N_NODES  = 16;
}

// Packed bf16 hi/lo planes (u32 = two adjacent-k bf16). Static device globals
// are the sanctioned scratch mechanism.
__device__ __align__(16) static uint32_t g_Whi[(size_t)N_NODES * NKP * ND];   // 128 MB
__device__ __align__(16) static uint32_t g_Wlo[(size_t)N_NODES * NKP * ND];   // 128 MB
__device__ __align__(16) static uint32_t g_S[2][2][(size_t)NBATCH * NKP];     // sum planes [slot][hi/lo]
__device__ __align__(16) static uint32_t g_Y[2][2][(size_t)NBATCH * NKP];     // activation planes

__device__ __forceinline__ uint32_t packu(__nv_bfloat16 a, __nv_bfloat16 b) {
    return (uint32_t)__bfloat16_as_ushort(a) | ((uint32_t)__bfloat16_as_ushort(b) << 16);
}
__device__ __forceinline__ void split2(float v0, float v1, uint32_t& hi, uint32_t& lo) {
    __nv_bfloat16 h0 = __float2bfloat16(v0), h1 = __float2bfloat16(v1);
    hi = packu(h0, h1);
    lo = packu(__float2bfloat16(v0 - __bfloat162float(h0)),
               __float2bfloat16(v1 - __bfloat162float(h1)));
}
__device__ __forceinline__ float lo16f(uint32_t v) {
    return __bfloat162float(__ushort_as_bfloat16((unsigned short)(v & 0xffffu)));
}
__device__ __forceinline__ float hi16f(uint32_t v) {
    return __bfloat162float(__ushort_as_bfloat16((unsigned short)(v >> 16)));
}

__device__ __forceinline__ void mma_bf16(float& c0, float& c1, float& c2, float& c3,
                                         uint32_t a0, uint32_t a1, uint32_t a2, uint32_t a3,
                                         uint32_t b0, uint32_t b1) {
    asm volatile(
        "mma.sync.aligned.m16n8k16.row.col.f32.bf16.bf16.f32 "
        "{%0,%1,%2,%3},{%4,%5,%6,%7},{%8,%9},{%0,%1,%2,%3};\n"
        : "+f"(c0), "+f"(c1), "+f"(c2), "+f"(c3)
        : "r"(a0), "r"(a1), "r"(a2), "r"(a3), "r"(b0), "r"(b1));
}

// ---------------------------------------------------------------------------
// Prepass: split W into k-pair-packed bf16 hi/lo planes (along k = W rows).
__global__ void split_w_kernel(const float* __restrict__ W) {
    size_t i = (size_t)blockIdx.x * NTHREADS + threadIdx.x;   // over 16*1024*2048
    size_t per_node = (size_t)NKP * ND;                       // 2^21
    int node = (int)(i >> 21);
    size_t rem = i & (per_node - 1);
    int kp  = (int)(rem >> 11);                                // /2048
    int col = (int)(rem & 2047);
    const float* p = W + (size_t)node * ND * ND + (size_t)(2 * kp) * ND + col;
    uint32_t hi, lo;
    split2(p[0], p[ND], hi, lo);
    g_Whi[i] = hi;
    g_Wlo[i] = lo;
}

// Split x (k = columns, adjacent) into g_S[0] planes.
__global__ void split_x_kernel(const float* __restrict__ x) {
    size_t i = (size_t)blockIdx.x * NTHREADS + threadIdx.x;   // over 4096*1024
    float2 v = reinterpret_cast<const float2*>(x)[i];
    uint32_t hi, lo;
    split2(v.x, v.y, hi, lo);
    g_S[0][0][i] = hi;
    g_S[0][1][i] = lo;
}

// ---------------------------------------------------------------------------
// One DAG node GEMM: reads A planes g_S[a_slot], B planes g_W*[node].
// Epilogue: tanh(+bias); writes y planes (yo_slot), s_{i+1} planes (so_slot,
// adding y_{i-1} from yp_slot), and/or fp32 d_out.
__global__ void __launch_bounds__(NTHREADS, 2)
dag_gemm(const float* __restrict__ bn, float* __restrict__ dout,
         int node, int a_slot, int yp_slot, int yo_slot, int so_slot, int write_out)
{
    extern __shared__ uint32_t sm[];

    const uint32_t* __restrict__ Ah = g_S[a_slot][0];
    const uint32_t* __restrict__ Al = g_S[a_slot][1];
    const uint32_t* __restrict__ Wh = g_Whi + (size_t)node * NKP * ND;
    const uint32_t* __restrict__ Wl = g_Wlo + (size_t)node * NKP * ND;

    const int tid  = threadIdx.x;
    const int lane = tid & 31;
    const int wid  = tid >> 5;
    const int g    = lane >> 2;
    const int t    = lane & 3;
    const int wm   = (wid >> 2) * 64;
    const int wn   = (wid & 3) * 32;
    const int m0   = blockIdx.y * BM;
    const int n0   = blockIdx.x * BN;

    const uint32_t smem_base = (uint32_t)__cvta_generic_to_shared(sm);

    float acc[4][4][4];
    #pragma unroll
    for (int mi = 0; mi < 4; mi++)
        #pragma unroll
        for (int ni = 0; ni < 4; ni++)
            #pragma unroll
            for (int q = 0; q < 4; q++)
                acc[mi][ni][q] = 0.0f;

    auto load_tiles = [&](int kt, int stg) {
        uint32_t sb = smem_base + (uint32_t)(stg * (STAGE_U32 * 4));
        // A tiles: 2 planes x 128 rows x 16 u32 -> 1024 x 16B chunks
        #pragma unroll
        for (int i = 0; i < 4; i++) {
            int e  = tid + i * NTHREADS;
            int pl = e >> 9;
            int r  = (e >> 2) & 127;
            int c  = e & 3;
            const uint32_t* src = (pl ? Al : Ah) + (size_t)(m0 + r) * NKP + kt * 16 + c * 4;
            uint32_t dst = sb + (uint32_t)((pl * APL + r * ASTR + c * 4) * 4);
            asm volatile("cp.async.cg.shared.global [%0], [%1], 16;\n" :: "r"(dst), "l"(src));
        }
        // B tiles: 2 planes x 16 kk x 128 u32 -> 1024 x 16B chunks
        #pragma unroll
        for (int i = 0; i < 4; i++) {
            int e  = tid + i * NTHREADS;
            int pl = e >> 9;
            int kk = (e >> 5) & 15;
            int c  = e & 31;
            const uint32_t* src = (pl ? Wl : Wh) + (size_t)(kt * 16 + kk) * ND + n0 + c * 4;
            uint32_t dst = sb + (uint32_t)((B_OFS + pl * BPL + kk * BSTR + c * 4) * 4);
            asm volatile("cp.async.cg.shared.global [%0], [%1], 16;\n" :: "r"(dst), "l"(src));
        }
        asm volatile("cp.async.commit_group;\n");
    };

    load_tiles(0, 0);

    #pragma unroll 1
    for (int kt = 0; kt < KTILES; ++kt) {
        const int cur = kt & 1;
        if (kt + 1 < KTILES) {
            load_tiles(kt + 1, cur ^ 1);
            asm volatile("cp.async.wait_group 1;\n");
        } else {
            asm volatile("cp.async.wait_group 0;\n");
        }
        __syncthreads();

        const int ab = cur * STAGE_U32;          // A hi base (u32 index into sm)
        #pragma unroll
        for (int s = 0; s < 2; s++) {
            uint32_t ah[4][4], al[4][4], bh[4][2], bl[4][2];
            #pragma unroll
            for (int ni = 0; ni < 4; ni++) {
                int c  = wn + ni * 8 + g;
                int r0 = ab + B_OFS + (s * 8 + t) * BSTR + c;
                bh[ni][0] = sm[r0];
                bh[ni][1] = sm[r0 + 4 * BSTR];
                bl[ni][0] = sm[r0 + BPL];
                bl[ni][1] = sm[r0 + BPL + 4 * BSTR];
            }
            #pragma unroll
            for (int mi = 0; mi < 4; mi++) {
                int r = wm + mi * 16 + g;
                int p = ab + r * ASTR + s * 8 + t;
                ah[mi][0] = sm[p];
                ah[mi][1] = sm[p + 8 * ASTR];
                ah[mi][2] = sm[p + 4];
                ah[mi][3] = sm[p + 8 * ASTR + 4];
                al[mi][0] = sm[p + APL];
                al[mi][1] = sm[p + APL + 8 * ASTR];
                al[mi][2] = sm[p + APL + 4];
                al[mi][3] = sm[p + APL + 8 * ASTR + 4];
            }
            // Term-major issue: all hh, then all hl, then all lh. Any given
            // accumulator is re-touched only every 16 MMAs -> RAW latency hidden.
            #pragma unroll
            for (int mi = 0; mi < 4; mi++)
                #pragma unroll
                for (int ni = 0; ni < 4; ni++)
                    mma_bf16(acc[mi][ni][0], acc[mi][ni][1], acc[mi][ni][2], acc[mi][ni][3],
                             ah[mi][0], ah[mi][1], ah[mi][2], ah[mi][3], bh[ni][0], bh[ni][1]);
            #pragma unroll
            for (int mi = 0; mi < 4; mi++)
                #pragma unroll
                for (int ni = 0; ni < 4; ni++)
                    mma_bf16(acc[mi][ni][0], acc[mi][ni][1], acc[mi][ni][2], acc[mi][ni][3],
                             ah[mi][0], ah[mi][1], ah[mi][2], ah[mi][3], bl[ni][0], bl[ni][1]);
            #pragma unroll
            for (int mi = 0; mi < 4; mi++)
                #pragma unroll
                for (int ni = 0; ni < 4; ni++)
                    mma_bf16(acc[mi][ni][0], acc[mi][ni][1], acc[mi][ni][2], acc[mi][ni][3],
                             al[mi][0], al[mi][1], al[mi][2], al[mi][3], bh[ni][0], bh[ni][1]);
        }
        __syncthreads();
    }

    // -------------------- epilogue --------------------
    uint32_t* __restrict__ Yoh = (yo_slot >= 0) ? g_Y[yo_slot][0] : nullptr;
    uint32_t* __restrict__ Yol = (yo_slot >= 0) ? g_Y[yo_slot][1] : nullptr;
    const uint32_t* __restrict__ Yph = (yp_slot >= 0) ? g_Y[yp_slot][0] : nullptr;
    const uint32_t* __restrict__ Ypl = (yp_slot >= 0) ? g_Y[yp_slot][1] : nullptr;
    uint32_t* __restrict__ Soh = (so_slot >= 0) ? g_S[so_slot][0] : nullptr;
    uint32_t* __restrict__ Sol = (so_slot >= 0) ? g_S[so_slot][1] : nullptr;

    #pragma unroll
    for (int mi = 0; mi < 4; mi++) {
        #pragma unroll
        for (int ni = 0; ni < 4; ni++) {
            int colp = ((n0 + wn + ni * 8) >> 1) + t;     // u32 column in planes
            float b0 = bn[2 * colp];
            float b1 = bn[2 * colp + 1];
            #pragma unroll
            for (int h = 0; h < 2; h++) {
                int row = m0 + wm + mi * 16 + g + h * 8;
                float t0 = tanhf(acc[mi][ni][2 * h]     + b0);
                float t1 = tanhf(acc[mi][ni][2 * h + 1] + b1);
                size_t idx = (size_t)row * NKP + colp;
                if (write_out) {
                    float2 r2;
                    r2.x = t0; r2.y = t1;
                    *reinterpret_cast<float2*>(dout + (size_t)row * ND + 2 * colp) = r2;
                }
                if (Yoh) {
                    uint32_t hi, lo;
                    split2(t0, t1, hi, lo);
                    Yoh[idx] = hi; Yol[idx] = lo;
                }
                if (Soh) {
                    float s0 = t0, s1 = t1;
                    if (Yph) {
                        uint32_t ph = Yph[idx], pl = Ypl[idx];
                        s0 += lo16f(ph) + lo16f(pl);
                        s1 += hi16f(ph) + hi16f(pl);
                    }
                    uint32_t hi, lo;
                    split2(s0, s1, hi, lo);
                    Soh[idx] = hi; Sol[idx] = lo;
                }
            }
        }
    }
}

extern "C" void kernel_launch(void* const* d_in, const int* in_sizes, int n_in,
                              void* d_out, int out_size) {
    const float* x = (const float*)d_in[0];          // [4096, 2048]
    const float* W = (const float*)d_in[1];          // [16, 2048, 2048]
    const float* b = (const float*)d_in[2];          // [16, 2048]
    float* out = (float*)d_out;                      // [4096, 2048]

    cudaFuncSetAttribute(dag_gemm, cudaFuncAttributeMaxDynamicSharedMemorySize, SMEM_BYTES);

    // Prepass: pack W and x into bf16 hi/lo k-pair planes.
    split_w_kernel<<<(N_NODES * NKP * ND) / NTHREADS, NTHREADS>>>(W);   // 131072 blocks
    split_x_kernel<<<(NBATCH * NKP) / NTHREADS, NTHREADS>>>(x);         // 16384 blocks

    dim3 grid(ND / BN, NBATCH / BM);                 // (16, 32) = 512 CTAs

    for (int i = 0; i < N_NODES; i++) {
        int a_slot = i & 1;                           // s_i planes (x for node 0)
        int yp = (i >= 1 && i <= 14) ? ((i - 1) & 1) : -1;   // y_{i-1} for the s-sum
        int yo = (i <= 13) ? (i & 1) : -1;            // y_i planes (consumed by node i+1 epilogue)
        int so = (i <= 14) ? ((i + 1) & 1) : -1;      // s_{i+1} planes
        int wo = (i == N_NODES - 1) ? 1 : 0;
        dag_gemm<<<grid, NTHREADS, SMEM_BYTES>>>(b + (size_t)i * ND, out,
                                                 i, a_slot, yp, yo, so, wo);
    }
}